// round 1
// baseline (speedup 1.0000x reference)
#include <cuda_runtime.h>
#include <cuda_bf16.h>
#include <math.h>
#include <stdint.h>

// Problem constants (fixed shapes)
#define MAXN 100000
#define MAXE 3200000
#define F_IN 512
#define F_OUT 256
#define ALPHA 0.2f
#define EPS_DEN 9e-15f

// ---------------- device scratch (no allocations allowed) ----------------
__device__ float g_h[(size_t)MAXN * F_OUT];   // h = xW + b   (102.4 MB)
__device__ float g_ssrc[MAXN];
__device__ float g_sdst[MAXN];
__device__ float g_rowsum[MAXN];
__device__ unsigned g_gmax_enc;
__device__ float g_gmax_f;
__device__ int g_is64;

// ---------------- helpers ----------------
__device__ __forceinline__ unsigned float_enc(float f) {
    unsigned b = __float_as_uint(f);
    return b ^ ((unsigned)((int)b >> 31) | 0x80000000u);
}
__device__ __forceinline__ float float_dec(unsigned u) {
    unsigned b = (u & 0x80000000u) ? (u ^ 0x80000000u) : ~u;
    return __uint_as_float(b);
}
__device__ __forceinline__ int get_idx(const void* edge, long long pos, int is64) {
    if (is64) return (int)((const long long*)edge)[pos];
    return ((const int*)edge)[pos];
}
__device__ __forceinline__ void red_add_f4(float4* addr, float4 v) {
    asm volatile("red.global.add.v4.f32 [%0], {%1,%2,%3,%4};"
                 :: "l"(addr), "f"(v.x), "f"(v.y), "f"(v.z), "f"(v.w) : "memory");
}

// ---------------- kernel 0: detect edge dtype ----------------
// If data is int32, u64 word j = edge32[2j] | (edge32[2j+1] << 32); high word is a
// random index in [0,100000) -> almost surely nonzero somewhere in the first 64.
// If data is int64 (values < 2^31), all high words are 0.
__global__ void probe_kernel(const unsigned long long* __restrict__ e) {
    unsigned any = 0;
    for (int i = 0; i < 64; i++) any |= (unsigned)(e[i] >> 32);
    g_is64 = (any == 0) ? 1 : 0;
}

// ---------------- kernel 1: init out / rowsum / gmax ----------------
__global__ void init_kernel(float4* __restrict__ out4, int N) {
    long long i = (long long)blockIdx.x * blockDim.x + threadIdx.x;
    long long nq = (long long)N * (F_OUT / 4);
    if (i < nq) out4[i] = make_float4(0.f, 0.f, 0.f, 0.f);
    if (i < N) g_rowsum[i] = 0.f;
    if (i == 0) g_gmax_enc = 0u;
}

// ---------------- kernel 2: h = x @ W + bias  (fp32 tiled SGEMM) ----------------
#define BM 64
#define BN 64
#define BK 32
__global__ __launch_bounds__(256) void gemm_kernel(
    const float* __restrict__ X, const float* __restrict__ W,
    const float* __restrict__ bias, int N)
{
    __shared__ float As[BM][BK + 4];   // padded, row 16B-aligned (36 floats)
    __shared__ float Bs[BK][BN];
    int tid = threadIdx.x;
    int row0 = blockIdx.x * BM;
    int col0 = blockIdx.y * BN;
    int tm = (tid / 16) * 4;
    int tn = (tid % 16) * 4;
    float acc[4][4] = {};

    for (int k0 = 0; k0 < F_IN; k0 += BK) {
        // load A tile: 64 rows x 32 k = 512 float4
        #pragma unroll
        for (int l = 0; l < 2; l++) {
            int q = tid + l * 256;
            int r = q >> 3, kq = (q & 7) * 4;
            float4 v = make_float4(0.f, 0.f, 0.f, 0.f);
            int grow = row0 + r;
            if (grow < N) v = *(const float4*)(X + (size_t)grow * F_IN + k0 + kq);
            *(float4*)&As[r][kq] = v;
        }
        // load B tile: 32 k x 64 cols = 512 float4
        #pragma unroll
        for (int l = 0; l < 2; l++) {
            int q = tid + l * 256;
            int kr = q >> 4, cq = (q & 15) * 4;
            *(float4*)&Bs[kr][cq] = *(const float4*)(W + (size_t)(k0 + kr) * F_OUT + col0 + cq);
        }
        __syncthreads();
        #pragma unroll
        for (int k = 0; k < BK; k++) {
            float a[4];
            #pragma unroll
            for (int i = 0; i < 4; i++) a[i] = As[tm + i][k];
            float4 b4 = *(const float4*)&Bs[k][tn];
            float b[4] = {b4.x, b4.y, b4.z, b4.w};
            #pragma unroll
            for (int i = 0; i < 4; i++)
                #pragma unroll
                for (int j = 0; j < 4; j++) acc[i][j] += a[i] * b[j];
        }
        __syncthreads();
    }
    #pragma unroll
    for (int i = 0; i < 4; i++) {
        int grow = row0 + tm + i;
        if (grow >= N) break;
        #pragma unroll
        for (int j = 0; j < 4; j++)
            g_h[(size_t)grow * F_OUT + col0 + tn + j] = acc[i][j] + bias[col0 + tn + j];
    }
}

// ---------------- kernel 3: per-node scores s_src = h.a_src, s_dst = h.a_dst ----
__global__ void scores_kernel(const float* __restrict__ a, int N) {
    int warp = (blockIdx.x * blockDim.x + threadIdx.x) >> 5;
    int lane = threadIdx.x & 31;
    if (warp >= N) return;
    const float4* hr = (const float4*)(g_h + (size_t)warp * F_OUT);
    const float4* a4 = (const float4*)a;
    float s1 = 0.f, s2 = 0.f;
    #pragma unroll
    for (int i = lane; i < F_OUT / 4; i += 32) {
        float4 h = hr[i];
        float4 as = a4[i];
        float4 ad = a4[F_OUT / 4 + i];
        s1 += h.x * as.x + h.y * as.y + h.z * as.z + h.w * as.w;
        s2 += h.x * ad.x + h.y * ad.y + h.z * ad.z + h.w * ad.w;
    }
    #pragma unroll
    for (int o = 16; o > 0; o >>= 1) {
        s1 += __shfl_down_sync(0xFFFFFFFFu, s1, o);
        s2 += __shfl_down_sync(0xFFFFFFFFu, s2, o);
    }
    if (lane == 0) { g_ssrc[warp] = s1; g_sdst[warp] = s2; }
}

// ---------------- kernel 4: global max of leakyrelu(edge score) ----------------
__global__ void edgemax_kernel(const void* __restrict__ edge, int E) {
    int is64 = g_is64;
    float m = -INFINITY;
    for (long long e = (long long)blockIdx.x * blockDim.x + threadIdx.x; e < E;
         e += (long long)gridDim.x * blockDim.x) {
        int u = get_idx(edge, e, is64);
        int v = get_idx(edge, (long long)E + e, is64);
        float z = g_ssrc[u] + g_sdst[v];
        z = (z > 0.f) ? z : ALPHA * z;
        m = fmaxf(m, z);
    }
    #pragma unroll
    for (int o = 16; o > 0; o >>= 1) m = fmaxf(m, __shfl_xor_sync(0xFFFFFFFFu, m, o));
    __shared__ float sm[8];
    int wid = threadIdx.x >> 5;
    if ((threadIdx.x & 31) == 0) sm[wid] = m;
    __syncthreads();
    if (threadIdx.x == 0) {
        float bm = sm[0];
        for (int i = 1; i < (int)(blockDim.x >> 5); i++) bm = fmaxf(bm, sm[i]);
        atomicMax(&g_gmax_enc, float_enc(bm));
    }
}

__global__ void decode_kernel() { g_gmax_f = float_dec(g_gmax_enc); }

// ---------------- kernel 5: scatter  out[src] += w_e * h[dst], rowsum[src] += w_e
__global__ __launch_bounds__(256) void scatter_kernel(
    const void* __restrict__ edge, float* __restrict__ out, int E)
{
    long long gwid = ((long long)blockIdx.x * blockDim.x + threadIdx.x) >> 5;
    if (gwid >= E) return;
    int lane = threadIdx.x & 31;
    int is64 = g_is64;
    int u = get_idx(edge, gwid, is64);
    int v = get_idx(edge, (long long)E + gwid, is64);
    float z = g_ssrc[u] + g_sdst[v];
    z = (z > 0.f) ? z : ALPHA * z;
    float w = expf(z - g_gmax_f);
    if (lane == 0) atomicAdd(&g_rowsum[u], w);
    const float4* hv = (const float4*)(g_h + (size_t)v * F_OUT);
    float4* ov = (float4*)(out + (size_t)u * F_OUT);
    #pragma unroll
    for (int i = lane; i < F_OUT / 4; i += 32) {
        float4 t = hv[i];
        t.x *= w; t.y *= w; t.z *= w; t.w *= w;
        red_add_f4(&ov[i], t);
    }
}

// ---------------- kernel 6: out = elu(out / (rowsum + eps)) ----------------
__global__ void finalize_kernel(float* __restrict__ out, int N) {
    long long i = (long long)blockIdx.x * blockDim.x + threadIdx.x;
    if (i >= (long long)N * F_OUT) return;
    float r = g_rowsum[i >> 8];   // F_OUT = 256
    float v = out[i] / (r + EPS_DEN);
    out[i] = (v > 0.f) ? v : expm1f(v);
}

// ---------------- launch ----------------
extern "C" void kernel_launch(void* const* d_in, const int* in_sizes, int n_in,
                              void* d_out, int out_size)
{
    const float* x    = (const float*)d_in[0];
    const void*  edge = d_in[1];
    const float* W    = (const float*)d_in[2];
    const float* a    = (const float*)d_in[3];
    const float* bias = (const float*)d_in[4];
    float* out = (float*)d_out;

    int N = in_sizes[0] / F_IN;    // 100000
    int E = in_sizes[1] / 2;       // 3200000 (element count same for int32/int64)

    probe_kernel<<<1, 1>>>((const unsigned long long*)edge);

    {
        long long tot = (long long)N * (F_OUT / 4);
        int nb = (int)((tot + 255) / 256);
        init_kernel<<<nb, 256>>>((float4*)out, N);
    }
    {
        dim3 grid((N + BM - 1) / BM, F_OUT / BN);
        gemm_kernel<<<grid, 256>>>(x, W, bias, N);
    }
    {
        long long threads = (long long)N * 32;
        int nb = (int)((threads + 255) / 256);
        scores_kernel<<<nb, 256>>>(a, N);
    }
    edgemax_kernel<<<1024, 256>>>(edge, E);
    decode_kernel<<<1, 1>>>();
    {
        long long threads = (long long)E * 32;
        int nb = (int)((threads + 255) / 256);
        scatter_kernel<<<nb, 256>>>(edge, out, E);
    }
    {
        long long tot = (long long)N * F_OUT;
        int nb = (int)((tot + 255) / 256);
        finalize_kernel<<<nb, 256>>>(out, N);
    }
}

// round 3
// speedup vs baseline: 1.1953x; 1.1953x over previous
#include <cuda_runtime.h>
#include <cuda_bf16.h>
#include <math.h>
#include <stdint.h>

#define MAXN 100000
#define MAXE 3200000
#define F_IN 512
#define F_OUT 256
#define ALPHA 0.2f
#define EPS_DEN 9e-15f

// ---------------- device scratch ----------------
__device__ float g_h[(size_t)MAXN * F_OUT];           // h = xW + b (102.4 MB)
__device__ __nv_bfloat16 g_WT_hi[F_OUT * F_IN];       // W^T split, [n][k]
__device__ __nv_bfloat16 g_WT_lo[F_OUT * F_IN];
__device__ float g_ssrc[MAXN];
__device__ float g_sdst[MAXN];
__device__ float g_rowsum[MAXN];
__device__ unsigned g_gmax_enc;
__device__ float g_gmax_f;
__device__ int g_is64;

// ---------------- helpers ----------------
__device__ __forceinline__ uint32_t smem_u32(const void* p) {
    uint32_t a;
    asm("{ .reg .u64 t; cvta.to.shared.u64 t, %1; cvt.u32.u64 %0, t; }" : "=r"(a) : "l"(p));
    return a;
}
__device__ __forceinline__ void ldsm_x4(uint32_t* r, uint32_t addr) {
    asm volatile("ldmatrix.sync.aligned.m8n8.x4.shared.b16 {%0,%1,%2,%3}, [%4];"
        : "=r"(r[0]), "=r"(r[1]), "=r"(r[2]), "=r"(r[3]) : "r"(addr));
}
__device__ __forceinline__ void mma_bf16(float* d, const uint32_t* a, const uint32_t* b) {
    asm volatile("mma.sync.aligned.m16n8k16.row.col.f32.bf16.bf16.f32 "
        "{%0,%1,%2,%3}, {%4,%5,%6,%7}, {%8,%9}, {%0,%1,%2,%3};"
        : "+f"(d[0]), "+f"(d[1]), "+f"(d[2]), "+f"(d[3])
        : "r"(a[0]), "r"(a[1]), "r"(a[2]), "r"(a[3]), "r"(b[0]), "r"(b[1]));
}
__device__ __forceinline__ unsigned float_enc(float f) {
    unsigned b = __float_as_uint(f);
    return b ^ ((unsigned)((int)b >> 31) | 0x80000000u);
}
__device__ __forceinline__ float float_dec(unsigned u) {
    unsigned b = (u & 0x80000000u) ? (u ^ 0x80000000u) : ~u;
    return __uint_as_float(b);
}
__device__ __forceinline__ int get_idx(const void* edge, long long pos, int is64) {
    if (is64) return (int)((const long long*)edge)[pos];
    return ((const int*)edge)[pos];
}
__device__ __forceinline__ void red_add_f4(float4* addr, float4 v) {
    asm volatile("red.global.add.v4.f32 [%0], {%1,%2,%3,%4};"
                 :: "l"(addr), "f"(v.x), "f"(v.y), "f"(v.z), "f"(v.w) : "memory");
}
__device__ __forceinline__ unsigned pack_bf2(__nv_bfloat16 a, __nv_bfloat16 b) {
    return ((unsigned)__bfloat16_as_ushort(b) << 16) | (unsigned)__bfloat16_as_ushort(a);
}

// ---------------- kernel 0: detect edge dtype ----------------
__global__ void probe_kernel(const unsigned long long* __restrict__ e) {
    unsigned any = 0;
    for (int i = 0; i < 64; i++) any |= (unsigned)(e[i] >> 32);
    g_is64 = (any == 0) ? 1 : 0;
}

// ---------------- kernel 1: split W into bf16 hi/lo, transposed [n][k] -------
__global__ void wsplit_kernel(const float* __restrict__ W) {
    int i = blockIdx.x * blockDim.x + threadIdx.x;
    if (i >= F_IN * F_OUT) return;
    int k = i >> 8, n = i & 255;
    float f = W[i];
    __nv_bfloat16 h = __float2bfloat16(f);
    float r = f - __bfloat162float(h);
    g_WT_hi[n * F_IN + k] = h;
    g_WT_lo[n * F_IN + k] = __float2bfloat16(r);
}

// ---------------- kernel 2: init out / rowsum / scores / gmax ----------------
__global__ void init_kernel(float4* __restrict__ out4, int N) {
    long long i = (long long)blockIdx.x * blockDim.x + threadIdx.x;
    long long nq = (long long)N * (F_OUT / 4);
    if (i < nq) out4[i] = make_float4(0.f, 0.f, 0.f, 0.f);
    if (i < N) { g_rowsum[i] = 0.f; g_ssrc[i] = 0.f; g_sdst[i] = 0.f; }
    if (i == 0) g_gmax_enc = 0u;
}

// ---------------- kernel 3: HMMA GEMM h = xW + b, fused scores ---------------
// CTA tile M=64 x N=256(full), K chunks of 32. 8 warps, layout 2(m) x 4(n),
// warp tile 32x64. 3-pass bf16 split: D += Ah*Bh + Ah*Bl + Al*Bh.
#define KC 32
#define NCHUNK (F_IN / KC)   // 16
// smem byte offsets (80B row stride: conflict-free ldmatrix, 16B aligned)
#define SB_HI 0
#define SB_LO 20480
#define SA_HI 40960
#define SA_LO 46080
#define SM_BIAS 51200
#define SM_AVEC 52224
#define SM_TOTAL 54272

__global__ __launch_bounds__(256) void gemm_mma_kernel(
    const float* __restrict__ X, const float* __restrict__ bias,
    const float* __restrict__ avec, int N)
{
    extern __shared__ char smem[];
    uint32_t sb = smem_u32(smem);
    int tid = threadIdx.x;
    int wid = tid >> 5;
    int lane = tid & 31;
    int row0 = blockIdx.x * 64;

    int wm = wid & 1;          // m sub-tile (0,1) -> rows wm*32..
    int wn = wid >> 1;         // n sub-tile (0..3) -> cols wn*64..
    int m0 = wm * 32;
    int n0 = wn * 64;

    float* sm_bias = (float*)(smem + SM_BIAS);
    float* sm_a = (float*)(smem + SM_AVEC);
    if (tid < 256) {
        sm_bias[tid] = bias[tid];
        sm_a[tid] = avec[tid];
        sm_a[tid + 256] = avec[tid + 256];
    }

    float acc[2][8][4];
    #pragma unroll
    for (int mi = 0; mi < 2; mi++)
        #pragma unroll
        for (int nf = 0; nf < 8; nf++)
            #pragma unroll
            for (int d = 0; d < 4; d++) acc[mi][nf][d] = 0.f;

    // per-lane ldmatrix addresses (fixed parts)
    uint32_t a_row = (uint32_t)(lane & 15);
    uint32_t a_byte = (uint32_t)((lane >> 4) * 16);
    uint32_t b_row = (uint32_t)(((lane >> 4) << 3) + (lane & 7));
    uint32_t b_byte = (uint32_t)(((lane >> 3) & 1) << 4);

    for (int ch = 0; ch < NCHUNK; ch++) {
        __syncthreads();
        // ---- load & split A chunk: 64 rows x 32 k fp32 (512 float4) ----
        #pragma unroll
        for (int i = 0; i < 2; i++) {
            int q = tid + i * 256;
            int r = q >> 3, kq = (q & 7) * 4;
            int grow = row0 + r;
            float4 v = make_float4(0.f, 0.f, 0.f, 0.f);
            if (grow < N)
                v = *(const float4*)(X + (size_t)grow * F_IN + ch * KC + kq);
            __nv_bfloat16 hx = __float2bfloat16(v.x), hy = __float2bfloat16(v.y);
            __nv_bfloat16 hz = __float2bfloat16(v.z), hw = __float2bfloat16(v.w);
            float lx = v.x - __bfloat162float(hx), ly = v.y - __bfloat162float(hy);
            float lz = v.z - __bfloat162float(hz), lw = v.w - __bfloat162float(hw);
            uint32_t off = (uint32_t)(r * 80 + kq * 2);
            *(uint2*)(smem + SA_HI + off) = make_uint2(pack_bf2(hx, hy), pack_bf2(hz, hw));
            *(uint2*)(smem + SA_LO + off) = make_uint2(
                pack_bf2(__float2bfloat16(lx), __float2bfloat16(ly)),
                pack_bf2(__float2bfloat16(lz), __float2bfloat16(lw)));
        }
        // ---- load B chunk (pre-split bf16): 256 n x 32 k, hi+lo ----
        #pragma unroll
        for (int i = 0; i < 4; i++) {
            int q = tid + i * 256;
            int n = q >> 2, part = q & 3;
            uint32_t dst = (uint32_t)(n * 80 + part * 16);
            size_t src = (size_t)n * (F_IN * 2) + ch * (KC * 2) + part * 16;
            *(uint4*)(smem + SB_HI + dst) = *(const uint4*)((const char*)g_WT_hi + src);
            *(uint4*)(smem + SB_LO + dst) = *(const uint4*)((const char*)g_WT_lo + src);
        }
        __syncthreads();

        // ---- MMA: 2 k16 steps ----
        #pragma unroll
        for (int ks = 0; ks < 2; ks++) {
            uint32_t kb = ks * 32;
            uint32_t ah[8], al[8], bh[16], bl[16];
            uint32_t aoff = (m0 + a_row) * 80 + kb + a_byte;
            ldsm_x4(&ah[0], sb + SA_HI + aoff);
            ldsm_x4(&ah[4], sb + SA_HI + aoff + 16 * 80);
            ldsm_x4(&al[0], sb + SA_LO + aoff);
            ldsm_x4(&al[4], sb + SA_LO + aoff + 16 * 80);
            #pragma unroll
            for (int g = 0; g < 4; g++) {
                uint32_t boff = (n0 + g * 16 + b_row) * 80 + kb + b_byte;
                ldsm_x4(&bh[g * 4], sb + SB_HI + boff);
                ldsm_x4(&bl[g * 4], sb + SB_LO + boff);
            }
            #pragma unroll
            for (int mi = 0; mi < 2; mi++)
                #pragma unroll
                for (int nf = 0; nf < 8; nf++) {
                    int bi = (nf >> 1) * 4 + (nf & 1) * 2;
                    mma_bf16(acc[mi][nf], &ah[mi * 4], &bh[bi]);
                    mma_bf16(acc[mi][nf], &ah[mi * 4], &bl[bi]);
                    mma_bf16(acc[mi][nf], &al[mi * 4], &bh[bi]);
                }
        }
    }

    // ---- epilogue: bias, fused scores, store h ----
    int quad = lane & 3;
    int tg = lane >> 2;
    float s1[4], s2[4];
    #pragma unroll
    for (int r = 0; r < 4; r++) { s1[r] = 0.f; s2[r] = 0.f; }

    #pragma unroll
    for (int mi = 0; mi < 2; mi++) {
        int rbase = row0 + m0 + mi * 16 + tg;
        #pragma unroll
        for (int half = 0; half < 2; half++) {
            int row = rbase + half * 8;
            int sidx = mi * 2 + half;
            if (row < N) {
                float* orow = g_h + (size_t)row * F_OUT;
                #pragma unroll
                for (int nf = 0; nf < 8; nf++) {
                    int col = n0 + nf * 8 + quad * 2;
                    float v0 = acc[mi][nf][half * 2 + 0] + sm_bias[col];
                    float v1 = acc[mi][nf][half * 2 + 1] + sm_bias[col + 1];
                    s1[sidx] += v0 * sm_a[col] + v1 * sm_a[col + 1];
                    s2[sidx] += v0 * sm_a[256 + col] + v1 * sm_a[256 + col + 1];
                    *(float2*)(orow + col) = make_float2(v0, v1);
                }
            }
        }
    }
    // quad reduction (lanes sharing a row are quad groups)
    #pragma unroll
    for (int r = 0; r < 4; r++) {
        #pragma unroll
        for (int o = 1; o < 4; o <<= 1) {
            s1[r] += __shfl_xor_sync(0xFFFFFFFFu, s1[r], o);
            s2[r] += __shfl_xor_sync(0xFFFFFFFFu, s2[r], o);
        }
    }
    if (quad == 0) {
        #pragma unroll
        for (int mi = 0; mi < 2; mi++)
            #pragma unroll
            for (int half = 0; half < 2; half++) {
                int row = row0 + m0 + mi * 16 + half * 8 + tg;
                if (row < N) {
                    atomicAdd(&g_ssrc[row], s1[mi * 2 + half]);
                    atomicAdd(&g_sdst[row], s2[mi * 2 + half]);
                }
            }
    }
}

// ---------------- kernel 4: global max of leakyrelu(edge score) --------------
__global__ void edgemax_kernel(const void* __restrict__ edge, int E) {
    int is64 = g_is64;
    float m = -INFINITY;
    for (long long e = (long long)blockIdx.x * blockDim.x + threadIdx.x; e < E;
         e += (long long)gridDim.x * blockDim.x) {
        int u = get_idx(edge, e, is64);
        int v = get_idx(edge, (long long)E + e, is64);
        float z = g_ssrc[u] + g_sdst[v];
        z = (z > 0.f) ? z : ALPHA * z;
        m = fmaxf(m, z);
    }
    #pragma unroll
    for (int o = 16; o > 0; o >>= 1) m = fmaxf(m, __shfl_xor_sync(0xFFFFFFFFu, m, o));
    __shared__ float sm[8];
    int wid = threadIdx.x >> 5;
    if ((threadIdx.x & 31) == 0) sm[wid] = m;
    __syncthreads();
    if (threadIdx.x == 0) {
        float bm = sm[0];
        for (int i = 1; i < (int)(blockDim.x >> 5); i++) bm = fmaxf(bm, sm[i]);
        atomicMax(&g_gmax_enc, float_enc(bm));
    }
}

__global__ void decode_kernel() { g_gmax_f = float_dec(g_gmax_enc); }

// ---------------- kernel 5: scatter out[src] += w_e * h[dst] ----------------
__global__ __launch_bounds__(256) void scatter_kernel(
    const void* __restrict__ edge, float* __restrict__ out, int E)
{
    long long gwid = ((long long)blockIdx.x * blockDim.x + threadIdx.x) >> 5;
    if (gwid >= E) return;
    int lane = threadIdx.x & 31;
    int is64 = g_is64;
    int u = get_idx(edge, gwid, is64);
    int v = get_idx(edge, (long long)E + gwid, is64);
    float z = g_ssrc[u] + g_sdst[v];
    z = (z > 0.f) ? z : ALPHA * z;
    float w = expf(z - g_gmax_f);
    if (lane == 0) atomicAdd(&g_rowsum[u], w);
    const float4* hv = (const float4*)(g_h + (size_t)v * F_OUT);
    float4* ov = (float4*)(out + (size_t)u * F_OUT);
    #pragma unroll
    for (int i = lane; i < F_OUT / 4; i += 32) {
        float4 t = hv[i];
        t.x *= w; t.y *= w; t.z *= w; t.w *= w;
        red_add_f4(&ov[i], t);
    }
}

// ---------------- kernel 6: out = elu(out / (rowsum + eps)) ----------------
__global__ void finalize_kernel(float* __restrict__ out, int N) {
    long long i = (long long)blockIdx.x * blockDim.x + threadIdx.x;
    if (i >= (long long)N * F_OUT) return;
    float r = g_rowsum[i >> 8];
    float v = out[i] / (r + EPS_DEN);
    out[i] = (v > 0.f) ? v : expm1f(v);
}

// ---------------- launch ----------------
extern "C" void kernel_launch(void* const* d_in, const int* in_sizes, int n_in,
                              void* d_out, int out_size)
{
    const float* x    = (const float*)d_in[0];
    const void*  edge = d_in[1];
    const float* W    = (const float*)d_in[2];
    const float* a    = (const float*)d_in[3];
    const float* bias = (const float*)d_in[4];
    float* out = (float*)d_out;

    int N = in_sizes[0] / F_IN;
    int E = in_sizes[1] / 2;

    static int smem_set = 0;
    if (!smem_set) {
        cudaFuncSetAttribute(gemm_mma_kernel, cudaFuncAttributeMaxDynamicSharedMemorySize, SM_TOTAL);
        smem_set = 1;
    }

    probe_kernel<<<1, 1>>>((const unsigned long long*)edge);
    wsplit_kernel<<<(F_IN * F_OUT + 255) / 256, 256>>>(W);
    {
        long long tot = (long long)N * (F_OUT / 4);
        init_kernel<<<(int)((tot + 255) / 256), 256>>>((float4*)out, N);
    }
    gemm_mma_kernel<<<(N + 63) / 64, 256, SM_TOTAL>>>(x, bias, a, N);
    edgemax_kernel<<<1024, 256>>>(edge, E);
    decode_kernel<<<1, 1>>>();
    {
        long long threads = (long long)E * 32;
        scatter_kernel<<<(int)((threads + 255) / 256), 256>>>(edge, out, E);
    }
    {
        long long tot = (long long)N * F_OUT;
        finalize_kernel<<<(int)((tot + 255) / 256), 256>>>(out, N);
    }
}

// round 6
// speedup vs baseline: 2.5934x; 2.1696x over previous
#include <cuda_runtime.h>
#include <cuda_bf16.h>
#include <math.h>
#include <stdint.h>

#define MAXN 100000
#define MAXE 3200000
#define F_IN 512
#define F_OUT 256
#define ALPHA 0.2f
#define EPS_DEN 9e-15f

// ---------------- device scratch ----------------
__device__ float g_h[(size_t)MAXN * F_OUT];           // h = xW + b (102.4 MB)
__device__ __nv_bfloat16 g_WT_hi[F_OUT * F_IN];       // W^T split, [n][k]
__device__ __nv_bfloat16 g_WT_lo[F_OUT * F_IN];
__device__ float g_ssrc[MAXN];
__device__ float g_sdst[MAXN];
__device__ int g_count[MAXN];
__device__ int g_offset[MAXN + 1];
__device__ int g_cursor[MAXN];
__device__ int g_bsum[128];
__device__ int g_dst32[MAXE];
__device__ unsigned g_gmax_enc;
__device__ float g_gmax_f;
__device__ int g_is64;

// ---------------- helpers ----------------
__device__ __forceinline__ uint32_t smem_u32(const void* p) {
    uint32_t a;
    asm("{ .reg .u64 t; cvta.to.shared.u64 t, %1; cvt.u32.u64 %0, t; }" : "=r"(a) : "l"(p));
    return a;
}
__device__ __forceinline__ void ldsm_x4(uint32_t* r, uint32_t addr) {
    asm volatile("ldmatrix.sync.aligned.m8n8.x4.shared.b16 {%0,%1,%2,%3}, [%4];"
        : "=r"(r[0]), "=r"(r[1]), "=r"(r[2]), "=r"(r[3]) : "r"(addr));
}
__device__ __forceinline__ void mma_bf16(float* d, const uint32_t* a, const uint32_t* b) {
    asm volatile("mma.sync.aligned.m16n8k16.row.col.f32.bf16.bf16.f32 "
        "{%0,%1,%2,%3}, {%4,%5,%6,%7}, {%8,%9}, {%0,%1,%2,%3};"
        : "+f"(d[0]), "+f"(d[1]), "+f"(d[2]), "+f"(d[3])
        : "r"(a[0]), "r"(a[1]), "r"(a[2]), "r"(a[3]), "r"(b[0]), "r"(b[1]));
}
__device__ __forceinline__ unsigned float_enc(float f) {
    unsigned b = __float_as_uint(f);
    return b ^ ((unsigned)((int)b >> 31) | 0x80000000u);
}
__device__ __forceinline__ float float_dec(unsigned u) {
    unsigned b = (u & 0x80000000u) ? (u ^ 0x80000000u) : ~u;
    return __uint_as_float(b);
}
__device__ __forceinline__ int get_idx(const void* edge, long long pos, int is64) {
    if (is64) return (int)((const long long*)edge)[pos];
    return ((const int*)edge)[pos];
}
__device__ __forceinline__ unsigned pack_bf2(__nv_bfloat16 a, __nv_bfloat16 b) {
    return ((unsigned)__bfloat16_as_ushort(b) << 16) | (unsigned)__bfloat16_as_ushort(a);
}

// ---------------- kernel 0: detect edge dtype ----------------
__global__ void probe_kernel(const unsigned long long* __restrict__ e) {
    unsigned any = 0;
    for (int i = 0; i < 64; i++) any |= (unsigned)(e[i] >> 32);
    g_is64 = (any == 0) ? 1 : 0;
}

// ---------------- kernel 1: split W into bf16 hi/lo, transposed [n][k] -------
__global__ void wsplit_kernel(const float* __restrict__ W) {
    int i = blockIdx.x * blockDim.x + threadIdx.x;
    if (i >= F_IN * F_OUT) return;
    int k = i >> 8, n = i & 255;
    float f = W[i];
    __nv_bfloat16 h = __float2bfloat16(f);
    float r = f - __bfloat162float(h);
    g_WT_hi[n * F_IN + k] = h;
    g_WT_lo[n * F_IN + k] = __float2bfloat16(r);
}

// ---------------- kernel 2: init scores / counters / gmax ----------------
__global__ void init_kernel(int N) {
    int i = blockIdx.x * blockDim.x + threadIdx.x;
    if (i < N) { g_ssrc[i] = 0.f; g_sdst[i] = 0.f; g_count[i] = 0; }
    if (i == 0) g_gmax_enc = 0u;
}

// ---------------- kernel 3: double-buffered HMMA GEMM h = xW + b + scores ----
#define KC 32
#define NCHUNK (F_IN / KC)   // 16
// per-buffer layout (80B row stride: conflict-free ldmatrix)
#define SB_HI 0
#define SB_LO 20480
#define SA_HI 40960
#define SA_LO 46080
#define BUF_SZ 51200
#define SM_BIAS (2 * BUF_SZ)          // 102400
#define SM_AVEC (SM_BIAS + 1024)
#define SM_TOTAL (SM_AVEC + 2048)     // 105472

__global__ __launch_bounds__(256) void gemm_mma_kernel(
    const float* __restrict__ X, const float* __restrict__ bias,
    const float* __restrict__ avec, int N)
{
    extern __shared__ char smem[];
    uint32_t sb = smem_u32(smem);
    int tid = threadIdx.x;
    int wid = tid >> 5;
    int lane = tid & 31;
    int row0 = blockIdx.x * 64;

    int wm = wid & 1;
    int wn = wid >> 1;
    int m0 = wm * 32;
    int n0 = wn * 64;

    float* sm_bias = (float*)(smem + SM_BIAS);
    float* sm_a = (float*)(smem + SM_AVEC);
    if (tid < 256) {
        sm_bias[tid] = bias[tid];
        sm_a[tid] = avec[tid];
        sm_a[tid + 256] = avec[tid + 256];
    }

    float acc[2][8][4];
    #pragma unroll
    for (int mi = 0; mi < 2; mi++)
        #pragma unroll
        for (int nf = 0; nf < 8; nf++)
            #pragma unroll
            for (int d = 0; d < 4; d++) acc[mi][nf][d] = 0.f;

    uint32_t a_row = (uint32_t)(lane & 15);
    uint32_t a_byte = (uint32_t)((lane >> 4) * 16);
    uint32_t b_row = (uint32_t)(((lane >> 4) << 3) + (lane & 7));
    uint32_t b_byte = (uint32_t)(((lane >> 3) & 1) << 4);

    // ---- staging registers ----
    float4 stA[2];
    uint4 stBh[4], stBl[4];
    int ar[2], akq[2];
    #pragma unroll
    for (int i = 0; i < 2; i++) {
        int q = tid + i * 256;
        ar[i] = q >> 3; akq[i] = (q & 7) * 4;
    }

    auto load_stage = [&](int ch) {
        #pragma unroll
        for (int i = 0; i < 2; i++) {
            int grow = row0 + ar[i];
            stA[i] = make_float4(0.f, 0.f, 0.f, 0.f);
            if (grow < N) stA[i] = *(const float4*)(X + (size_t)grow * F_IN + ch * KC + akq[i]);
        }
        #pragma unroll
        for (int i = 0; i < 4; i++) {
            int q = tid + i * 256;
            int n = q >> 2, part = q & 3;
            size_t src = (size_t)n * (F_IN * 2) + ch * (KC * 2) + part * 16;
            stBh[i] = *(const uint4*)((const char*)g_WT_hi + src);
            stBl[i] = *(const uint4*)((const char*)g_WT_lo + src);
        }
    };
    auto store_stage = [&](int buf) {
        char* base = smem + buf * BUF_SZ;
        #pragma unroll
        for (int i = 0; i < 2; i++) {
            float4 v = stA[i];
            __nv_bfloat16 hx = __float2bfloat16(v.x), hy = __float2bfloat16(v.y);
            __nv_bfloat16 hz = __float2bfloat16(v.z), hw = __float2bfloat16(v.w);
            float lx = v.x - __bfloat162float(hx), ly = v.y - __bfloat162float(hy);
            float lz = v.z - __bfloat162float(hz), lw = v.w - __bfloat162float(hw);
            uint32_t off = (uint32_t)(ar[i] * 80 + akq[i] * 2);
            *(uint2*)(base + SA_HI + off) = make_uint2(pack_bf2(hx, hy), pack_bf2(hz, hw));
            *(uint2*)(base + SA_LO + off) = make_uint2(
                pack_bf2(__float2bfloat16(lx), __float2bfloat16(ly)),
                pack_bf2(__float2bfloat16(lz), __float2bfloat16(lw)));
        }
        #pragma unroll
        for (int i = 0; i < 4; i++) {
            int q = tid + i * 256;
            int n = q >> 2, part = q & 3;
            uint32_t dst = (uint32_t)(n * 80 + part * 16);
            *(uint4*)(base + SB_HI + dst) = stBh[i];
            *(uint4*)(base + SB_LO + dst) = stBl[i];
        }
    };

    load_stage(0);
    store_stage(0);

    for (int ch = 0; ch < NCHUNK; ch++) {
        __syncthreads();                 // buf[ch&1] filled; prev readers done
        if (ch + 1 < NCHUNK) load_stage(ch + 1);
        uint32_t bufb = sb + (uint32_t)((ch & 1) * BUF_SZ);
        // ---- MMA: 2 k16 steps ----
        #pragma unroll
        for (int ks = 0; ks < 2; ks++) {
            uint32_t kb = ks * 32;
            uint32_t ah[8], al[8], bh[16], bl[16];
            uint32_t aoff = (m0 + a_row) * 80 + kb + a_byte;
            ldsm_x4(&ah[0], bufb + SA_HI + aoff);
            ldsm_x4(&ah[4], bufb + SA_HI + aoff + 16 * 80);
            ldsm_x4(&al[0], bufb + SA_LO + aoff);
            ldsm_x4(&al[4], bufb + SA_LO + aoff + 16 * 80);
            #pragma unroll
            for (int g = 0; g < 4; g++) {
                uint32_t boff = (n0 + g * 16 + b_row) * 80 + kb + b_byte;
                ldsm_x4(&bh[g * 4], bufb + SB_HI + boff);
                ldsm_x4(&bl[g * 4], bufb + SB_LO + boff);
            }
            #pragma unroll
            for (int mi = 0; mi < 2; mi++)
                #pragma unroll
                for (int nf = 0; nf < 8; nf++) {
                    int bi = (nf >> 1) * 4 + (nf & 1) * 2;
                    mma_bf16(acc[mi][nf], &ah[mi * 4], &bh[bi]);
                    mma_bf16(acc[mi][nf], &ah[mi * 4], &bl[bi]);
                    mma_bf16(acc[mi][nf], &al[mi * 4], &bh[bi]);
                }
        }
        if (ch + 1 < NCHUNK) store_stage((ch + 1) & 1);
    }

    // ---- epilogue: bias, fused scores, store h ----
    int quad = lane & 3;
    int tg = lane >> 2;
    float s1[4], s2[4];
    #pragma unroll
    for (int r = 0; r < 4; r++) { s1[r] = 0.f; s2[r] = 0.f; }

    #pragma unroll
    for (int mi = 0; mi < 2; mi++) {
        #pragma unroll
        for (int half = 0; half < 2; half++) {
            int row = row0 + m0 + mi * 16 + half * 8 + tg;
            int sidx = mi * 2 + half;
            if (row < N) {
                float* orow = g_h + (size_t)row * F_OUT;
                #pragma unroll
                for (int nf = 0; nf < 8; nf++) {
                    int col = n0 + nf * 8 + quad * 2;
                    float v0 = acc[mi][nf][half * 2 + 0] + sm_bias[col];
                    float v1 = acc[mi][nf][half * 2 + 1] + sm_bias[col + 1];
                    s1[sidx] += v0 * sm_a[col] + v1 * sm_a[col + 1];
                    s2[sidx] += v0 * sm_a[256 + col] + v1 * sm_a[256 + col + 1];
                    *(float2*)(orow + col) = make_float2(v0, v1);
                }
            }
        }
    }
    #pragma unroll
    for (int r = 0; r < 4; r++) {
        #pragma unroll
        for (int o = 1; o < 4; o <<= 1) {
            s1[r] += __shfl_xor_sync(0xFFFFFFFFu, s1[r], o);
            s2[r] += __shfl_xor_sync(0xFFFFFFFFu, s2[r], o);
        }
    }
    if (quad == 0) {
        #pragma unroll
        for (int mi = 0; mi < 2; mi++)
            #pragma unroll
            for (int half = 0; half < 2; half++) {
                int row = row0 + m0 + mi * 16 + half * 8 + tg;
                if (row < N) {
                    atomicAdd(&g_ssrc[row], s1[mi * 2 + half]);
                    atomicAdd(&g_sdst[row], s2[mi * 2 + half]);
                }
            }
    }
}

// ---------------- kernel 4: histogram by src + global edge max ---------------
__global__ void hist_kernel(const void* __restrict__ edge, int E) {
    int is64 = g_is64;
    float m = -INFINITY;
    for (long long e = (long long)blockIdx.x * blockDim.x + threadIdx.x; e < E;
         e += (long long)gridDim.x * blockDim.x) {
        int u = get_idx(edge, e, is64);
        int v = get_idx(edge, (long long)E + e, is64);
        atomicAdd(&g_count[u], 1);
        float z = g_ssrc[u] + g_sdst[v];
        z = (z > 0.f) ? z : ALPHA * z;
        m = fmaxf(m, z);
    }
    #pragma unroll
    for (int o = 16; o > 0; o >>= 1) m = fmaxf(m, __shfl_xor_sync(0xFFFFFFFFu, m, o));
    __shared__ float sm[8];
    int wid = threadIdx.x >> 5;
    if ((threadIdx.x & 31) == 0) sm[wid] = m;
    __syncthreads();
    if (threadIdx.x == 0) {
        float bm = sm[0];
        for (int i = 1; i < (int)(blockDim.x >> 5); i++) bm = fmaxf(bm, sm[i]);
        atomicMax(&g_gmax_enc, float_enc(bm));
    }
}

__global__ void decode_kernel() { g_gmax_f = float_dec(g_gmax_enc); }

// ---------------- scan kernels: exclusive prefix sum of g_count -> g_offset --
__global__ __launch_bounds__(1024) void scan1_kernel(int N) {
    __shared__ int s[1024];
    int tid = threadIdx.x;
    int i = blockIdx.x * 1024 + tid;
    int v = (i < N) ? g_count[i] : 0;
    s[tid] = v;
    __syncthreads();
    #pragma unroll
    for (int off = 1; off < 1024; off <<= 1) {
        int t = (tid >= off) ? s[tid - off] : 0;
        __syncthreads();
        s[tid] += t;
        __syncthreads();
    }
    if (i < N) g_offset[i] = s[tid] - v;       // exclusive within block
    if (tid == 1023) g_bsum[blockIdx.x] = s[1023];
}

__global__ __launch_bounds__(128) void scan2_kernel(int nb) {
    __shared__ int s[128];
    int tid = threadIdx.x;
    int v = (tid < nb) ? g_bsum[tid] : 0;
    s[tid] = v;
    __syncthreads();
    #pragma unroll
    for (int off = 1; off < 128; off <<= 1) {
        int t = (tid >= off) ? s[tid - off] : 0;
        __syncthreads();
        s[tid] += t;
        __syncthreads();
    }
    if (tid < nb) g_bsum[tid] = s[tid] - v;    // exclusive
}

__global__ void scan3_kernel(int N, int E) {
    int i = blockIdx.x * blockDim.x + threadIdx.x;
    if (i < N) {
        int off = g_offset[i] + g_bsum[i >> 10];
        g_offset[i] = off;
        g_cursor[i] = off;
    }
    if (i == 0) g_offset[N] = E;
}

// ---------------- kernel 5: place edges sorted by src ------------------------
__global__ void place_kernel(const void* __restrict__ edge, int E) {
    int is64 = g_is64;
    for (long long e = (long long)blockIdx.x * blockDim.x + threadIdx.x; e < E;
         e += (long long)gridDim.x * blockDim.x) {
        int u = get_idx(edge, e, is64);
        int v = get_idx(edge, (long long)E + e, is64);
        int pos = atomicAdd(&g_cursor[u], 1);
        g_dst32[pos] = v;
    }
}

// ---------------- kernel 6: per-node aggregate + finalize --------------------
__global__ __launch_bounds__(256) void agg_kernel(float* __restrict__ out, int N) {
    int u = (blockIdx.x * blockDim.x + threadIdx.x) >> 5;
    if (u >= N) return;
    int lane = threadIdx.x & 31;
    int beg = g_offset[u], end = g_offset[u + 1];
    float su = g_ssrc[u];
    float gm = g_gmax_f;
    float4 acc0 = make_float4(0.f, 0.f, 0.f, 0.f);
    float4 acc1 = make_float4(0.f, 0.f, 0.f, 0.f);
    float rs = 0.f;

    for (int base = beg; base < end; base += 32) {
        int cnt = min(32, end - base);
        int v = 0; float wg = 0.f;
        if (lane < cnt) {
            v = g_dst32[base + lane];
            float z = su + g_sdst[v];
            z = (z > 0.f) ? z : ALPHA * z;
            wg = __expf(z - gm);
        }
        for (int i = 0; i < cnt; i++) {
            int vi = __shfl_sync(0xFFFFFFFFu, v, i);
            float wi = __shfl_sync(0xFFFFFFFFu, wg, i);
            const float4* hv = (const float4*)(g_h + (size_t)vi * F_OUT) + lane * 2;
            float4 p0 = hv[0], p1 = hv[1];
            acc0.x += wi * p0.x; acc0.y += wi * p0.y; acc0.z += wi * p0.z; acc0.w += wi * p0.w;
            acc1.x += wi * p1.x; acc1.y += wi * p1.y; acc1.z += wi * p1.z; acc1.w += wi * p1.w;
            rs += wi;
        }
    }
    float inv = 1.f / (rs + EPS_DEN);
    float4 o0, o1;
    o0.x = acc0.x * inv; o0.y = acc0.y * inv; o0.z = acc0.z * inv; o0.w = acc0.w * inv;
    o1.x = acc1.x * inv; o1.y = acc1.y * inv; o1.z = acc1.z * inv; o1.w = acc1.w * inv;
    o0.x = (o0.x > 0.f) ? o0.x : expm1f(o0.x);
    o0.y = (o0.y > 0.f) ? o0.y : expm1f(o0.y);
    o0.z = (o0.z > 0.f) ? o0.z : expm1f(o0.z);
    o0.w = (o0.w > 0.f) ? o0.w : expm1f(o0.w);
    o1.x = (o1.x > 0.f) ? o1.x : expm1f(o1.x);
    o1.y = (o1.y > 0.f) ? o1.y : expm1f(o1.y);
    o1.z = (o1.z > 0.f) ? o1.z : expm1f(o1.z);
    o1.w = (o1.w > 0.f) ? o1.w : expm1f(o1.w);
    float4* op = (float4*)(out + (size_t)u * F_OUT) + lane * 2;
    op[0] = o0;
    op[1] = o1;
}

// ---------------- launch ----------------
extern "C" void kernel_launch(void* const* d_in, const int* in_sizes, int n_in,
                              void* d_out, int out_size)
{
    const float* x    = (const float*)d_in[0];
    const void*  edge = d_in[1];
    const float* W    = (const float*)d_in[2];
    const float* a    = (const float*)d_in[3];
    const float* bias = (const float*)d_in[4];
    float* out = (float*)d_out;

    int N = in_sizes[0] / F_IN;
    int E = in_sizes[1] / 2;

    static int smem_set = 0;
    if (!smem_set) {
        cudaFuncSetAttribute(gemm_mma_kernel, cudaFuncAttributeMaxDynamicSharedMemorySize, SM_TOTAL);
        smem_set = 1;
    }

    int nb_scan = (N + 1023) / 1024;

    probe_kernel<<<1, 1>>>((const unsigned long long*)edge);
    wsplit_kernel<<<(F_IN * F_OUT + 255) / 256, 256>>>(W);
    init_kernel<<<(N + 255) / 256, 256>>>(N);
    gemm_mma_kernel<<<(N + 63) / 64, 256, SM_TOTAL>>>(x, bias, a, N);
    hist_kernel<<<1024, 256>>>(edge, E);
    decode_kernel<<<1, 1>>>();
    scan1_kernel<<<nb_scan, 1024>>>(N);
    scan2_kernel<<<1, 128>>>(nb_scan);
    scan3_kernel<<<(N + 255) / 256, 256>>>(N, E);
    place_kernel<<<1024, 256>>>(edge, E);
    {
        long long threads = (long long)N * 32;
        agg_kernel<<<(int)((threads + 255) / 256), 256>>>(out, N);
    }
}

// round 16
// speedup vs baseline: 3.2085x; 1.2372x over previous
#include <cuda_runtime.h>
#include <cuda_bf16.h>
#include <cuda_fp16.h>
#include <math.h>
#include <stdint.h>

#define MAXN 100000
#define MAXE 3200000
#define F_IN 512
#define F_OUT 256
#define ALPHA 0.2f
#define EPS_DEN 9e-15f

// ---------------- device scratch ----------------
__device__ __align__(16) __half g_h16[(size_t)MAXN * F_OUT];  // h in fp16 (51.2 MB)
__device__ __nv_bfloat16 g_WT_hi[F_OUT * F_IN];               // W^T split, [n][k]
__device__ __nv_bfloat16 g_WT_lo[F_OUT * F_IN];
__device__ float g_ssrc[MAXN];
__device__ float g_sdst[MAXN];
__device__ int g_count[MAXN];
__device__ int g_offset[MAXN + 1];
__device__ int g_cursor[MAXN];
__device__ int g_bsum[128];
__device__ int g_dst32[MAXE];
__device__ unsigned g_maxs_enc;     // max over g_ssrc (encoded)
__device__ unsigned g_maxd_enc;     // max over g_sdst (encoded)
__device__ float g_shiftC;          // C = max_s + max_d  (>= max edge score)
__device__ int g_is64;

// ---------------- helpers ----------------
__device__ __forceinline__ uint32_t smem_u32(const void* p) {
    uint32_t a;
    asm("{ .reg .u64 t; cvta.to.shared.u64 t, %1; cvt.u32.u64 %0, t; }" : "=r"(a) : "l"(p));
    return a;
}
__device__ __forceinline__ void ldsm_x4(uint32_t* r, uint32_t addr) {
    asm volatile("ldmatrix.sync.aligned.m8n8.x4.shared.b16 {%0,%1,%2,%3}, [%4];"
        : "=r"(r[0]), "=r"(r[1]), "=r"(r[2]), "=r"(r[3]) : "r"(addr));
}
__device__ __forceinline__ void mma_bf16(float* d, const uint32_t* a, const uint32_t* b) {
    asm volatile("mma.sync.aligned.m16n8k16.row.col.f32.bf16.bf16.f32 "
        "{%0,%1,%2,%3}, {%4,%5,%6,%7}, {%8,%9}, {%0,%1,%2,%3};"
        : "+f"(d[0]), "+f"(d[1]), "+f"(d[2]), "+f"(d[3])
        : "r"(a[0]), "r"(a[1]), "r"(a[2]), "r"(a[3]), "r"(b[0]), "r"(b[1]));
}
__device__ __forceinline__ void cp16(uint32_t dst, const void* src) {
    asm volatile("cp.async.cg.shared.global [%0], [%1], 16;" :: "r"(dst), "l"(src));
}
#define CP_COMMIT() asm volatile("cp.async.commit_group;" ::: "memory")
#define CP_WAIT0()  asm volatile("cp.async.wait_group 0;" ::: "memory")

__device__ __forceinline__ unsigned float_enc(float f) {
    unsigned b = __float_as_uint(f);
    return b ^ ((unsigned)((int)b >> 31) | 0x80000000u);
}
__device__ __forceinline__ float float_dec(unsigned u) {
    unsigned b = (u & 0x80000000u) ? (u ^ 0x80000000u) : ~u;
    return __uint_as_float(b);
}
__device__ __forceinline__ int get_idx(const void* edge, long long pos, int is64) {
    if (is64) return (int)((const long long*)edge)[pos];
    return ((const int*)edge)[pos];
}
__device__ __forceinline__ unsigned pack_bf2(__nv_bfloat16 a, __nv_bfloat16 b) {
    return ((unsigned)__bfloat16_as_ushort(b) << 16) | (unsigned)__bfloat16_as_ushort(a);
}

// ---------------- kernel 0: detect edge dtype ----------------
__global__ void probe_kernel(const unsigned long long* __restrict__ e) {
    unsigned any = 0;
    for (int i = 0; i < 64; i++) any |= (unsigned)(e[i] >> 32);
    g_is64 = (any == 0) ? 1 : 0;
}

// ---------------- kernel 1: split W into bf16 hi/lo, transposed [n][k] -------
__global__ void wsplit_kernel(const float* __restrict__ W) {
    int i = blockIdx.x * blockDim.x + threadIdx.x;
    if (i >= F_IN * F_OUT) return;
    int k = i >> 8, n = i & 255;
    float f = W[i];
    __nv_bfloat16 h = __float2bfloat16(f);
    float r = f - __bfloat162float(h);
    g_WT_hi[n * F_IN + k] = h;
    g_WT_lo[n * F_IN + k] = __float2bfloat16(r);
}

// ---------------- kernel 2: init scores / counters / maxes ----------------
__global__ void init_kernel(int N) {
    int i = blockIdx.x * blockDim.x + threadIdx.x;
    if (i < N) { g_ssrc[i] = 0.f; g_sdst[i] = 0.f; g_count[i] = 0; }
    if (i == 0) { g_maxs_enc = 0u; g_maxd_enc = 0u; }
}

// ---------------- kernel 3: cp.async double-buffered HMMA GEMM ---------------
#define KC 32
#define NCHUNK (F_IN / KC)   // 16
// per-buffer layout (80B row stride: conflict-free ldmatrix)
#define SB_HI 0
#define SB_LO 20480
#define SA_HI 40960
#define SA_LO 46080
#define BUF_SZ 51200
#define SM_BIAS (2 * BUF_SZ)          // 102400
#define SM_AVEC (SM_BIAS + 1024)
#define SM_TOTAL (SM_AVEC + 2048)     // 105472

__global__ __launch_bounds__(256) void gemm_mma_kernel(
    const float* __restrict__ X, const float* __restrict__ bias,
    const float* __restrict__ avec, int N)
{
    extern __shared__ char smem[];
    uint32_t sb = smem_u32(smem);
    int tid = threadIdx.x;
    int wid = tid >> 5;
    int lane = tid & 31;
    int row0 = blockIdx.x * 64;

    int wm = wid & 1;
    int wn = wid >> 1;
    int m0 = wm * 32;
    int n0 = wn * 64;

    float* sm_bias = (float*)(smem + SM_BIAS);
    float* sm_a = (float*)(smem + SM_AVEC);
    if (tid < 256) {
        sm_bias[tid] = bias[tid];
        sm_a[tid] = avec[tid];
        sm_a[tid + 256] = avec[tid + 256];
    }

    float acc[2][8][4];
    #pragma unroll
    for (int mi = 0; mi < 2; mi++)
        #pragma unroll
        for (int nf = 0; nf < 8; nf++)
            #pragma unroll
            for (int d = 0; d < 4; d++) acc[mi][nf][d] = 0.f;

    uint32_t a_row = (uint32_t)(lane & 15);
    uint32_t a_byte = (uint32_t)((lane >> 4) * 16);
    uint32_t b_row = (uint32_t)(((lane >> 4) << 3) + (lane & 7));
    uint32_t b_byte = (uint32_t)(((lane >> 3) & 1) << 4);

    // ---- A staging regs + fixed indices ----
    float4 stA[2];
    int ar[2], akq[2];
    #pragma unroll
    for (int i = 0; i < 2; i++) {
        int q = tid + i * 256;
        ar[i] = q >> 3; akq[i] = (q & 7) * 4;
    }
    // B cp.async fixed indices
    int bn[4], bpart[4];
    #pragma unroll
    for (int i = 0; i < 4; i++) {
        int q = tid + i * 256;
        bn[i] = q >> 2; bpart[i] = q & 3;
    }

    auto load_A = [&](int ch) {
        #pragma unroll
        for (int i = 0; i < 2; i++) {
            int grow = row0 + ar[i];
            stA[i] = make_float4(0.f, 0.f, 0.f, 0.f);
            if (grow < N) stA[i] = *(const float4*)(X + (size_t)grow * F_IN + ch * KC + akq[i]);
        }
    };
    auto store_A = [&](int buf) {
        char* base = smem + buf * BUF_SZ;
        #pragma unroll
        for (int i = 0; i < 2; i++) {
            float4 v = stA[i];
            __nv_bfloat16 hx = __float2bfloat16(v.x), hy = __float2bfloat16(v.y);
            __nv_bfloat16 hz = __float2bfloat16(v.z), hw = __float2bfloat16(v.w);
            float lx = v.x - __bfloat162float(hx), ly = v.y - __bfloat162float(hy);
            float lz = v.z - __bfloat162float(hz), lw = v.w - __bfloat162float(hw);
            uint32_t off = (uint32_t)(ar[i] * 80 + akq[i] * 2);
            *(uint2*)(base + SA_HI + off) = make_uint2(pack_bf2(hx, hy), pack_bf2(hz, hw));
            *(uint2*)(base + SA_LO + off) = make_uint2(
                pack_bf2(__float2bfloat16(lx), __float2bfloat16(ly)),
                pack_bf2(__float2bfloat16(lz), __float2bfloat16(lw)));
        }
    };
    auto issue_B = [&](int ch, int buf) {
        uint32_t base = sb + (uint32_t)(buf * BUF_SZ);
        #pragma unroll
        for (int i = 0; i < 4; i++) {
            uint32_t dst = (uint32_t)(bn[i] * 80 + bpart[i] * 16);
            size_t src = (size_t)bn[i] * (F_IN * 2) + ch * (KC * 2) + bpart[i] * 16;
            cp16(base + SB_HI + dst, (const char*)g_WT_hi + src);
            cp16(base + SB_LO + dst, (const char*)g_WT_lo + src);
        }
        CP_COMMIT();
    };

    // prologue: chunk 0 into buf 0
    load_A(0);
    store_A(0);
    issue_B(0, 0);
    CP_WAIT0();
    __syncthreads();

    for (int ch = 0; ch < NCHUNK; ch++) {
        int cur = ch & 1;
        if (ch + 1 < NCHUNK) {
            load_A(ch + 1);
            issue_B(ch + 1, 1 - cur);
        }
        uint32_t bufb = sb + (uint32_t)(cur * BUF_SZ);
        // ---- MMA: 2 k16 steps ----
        #pragma unroll
        for (int ks = 0; ks < 2; ks++) {
            uint32_t kb = ks * 32;
            uint32_t ah[8], al[8], bh[16], bl[16];
            uint32_t aoff = (m0 + a_row) * 80 + kb + a_byte;
            ldsm_x4(&ah[0], bufb + SA_HI + aoff);
            ldsm_x4(&ah[4], bufb + SA_HI + aoff + 16 * 80);
            ldsm_x4(&al[0], bufb + SA_LO + aoff);
            ldsm_x4(&al[4], bufb + SA_LO + aoff + 16 * 80);
            #pragma unroll
            for (int g = 0; g < 4; g++) {
                uint32_t boff = (n0 + g * 16 + b_row) * 80 + kb + b_byte;
                ldsm_x4(&bh[g * 4], bufb + SB_HI + boff);
                ldsm_x4(&bl[g * 4], bufb + SB_LO + boff);
            }
            #pragma unroll
            for (int mi = 0; mi < 2; mi++)
                #pragma unroll
                for (int nf = 0; nf < 8; nf++) {
                    int bi = (nf >> 1) * 4 + (nf & 1) * 2;
                    mma_bf16(acc[mi][nf], &ah[mi * 4], &bh[bi]);
                    mma_bf16(acc[mi][nf], &ah[mi * 4], &bl[bi]);
                    mma_bf16(acc[mi][nf], &al[mi * 4], &bh[bi]);
                }
        }
        if (ch + 1 < NCHUNK) {
            store_A(1 - cur);
            CP_WAIT0();
        }
        __syncthreads();
    }

    // ---- epilogue: bias, fused scores, store h as fp16 ----
    int quad = lane & 3;
    int tg = lane >> 2;
    float s1[4], s2[4];
    #pragma unroll
    for (int r = 0; r < 4; r++) { s1[r] = 0.f; s2[r] = 0.f; }

    #pragma unroll
    for (int mi = 0; mi < 2; mi++) {
        #pragma unroll
        for (int half = 0; half < 2; half++) {
            int row = row0 + m0 + mi * 16 + half * 8 + tg;
            int sidx = mi * 2 + half;
            if (row < N) {
                __half* hrow = g_h16 + (size_t)row * F_OUT;
                #pragma unroll
                for (int nf = 0; nf < 8; nf++) {
                    int col = n0 + nf * 8 + quad * 2;
                    float v0 = acc[mi][nf][half * 2 + 0] + sm_bias[col];
                    float v1 = acc[mi][nf][half * 2 + 1] + sm_bias[col + 1];
                    s1[sidx] += v0 * sm_a[col] + v1 * sm_a[col + 1];
                    s2[sidx] += v0 * sm_a[256 + col] + v1 * sm_a[256 + col + 1];
                    *(__half2*)(hrow + col) = __floats2half2_rn(v0, v1);
                }
            }
        }
    }
    #pragma unroll
    for (int r = 0; r < 4; r++) {
        #pragma unroll
        for (int o = 1; o < 4; o <<= 1) {
            s1[r] += __shfl_xor_sync(0xFFFFFFFFu, s1[r], o);
            s2[r] += __shfl_xor_sync(0xFFFFFFFFu, s2[r], o);
        }
    }
    if (quad == 0) {
        #pragma unroll
        for (int mi = 0; mi < 2; mi++)
            #pragma unroll
            for (int half = 0; half < 2; half++) {
                int row = row0 + m0 + mi * 16 + half * 8 + tg;
                if (row < N) {
                    atomicAdd(&g_ssrc[row], s1[mi * 2 + half]);
                    atomicAdd(&g_sdst[row], s2[mi * 2 + half]);
                }
            }
    }
}

// ---------------- kernel 4: node-level maxes (stable-shift upper bound) ------
__global__ void nodemax_kernel(int N) {
    float ms = -INFINITY, md = -INFINITY;
    for (int i = blockIdx.x * blockDim.x + threadIdx.x; i < N;
         i += gridDim.x * blockDim.x) {
        ms = fmaxf(ms, g_ssrc[i]);
        md = fmaxf(md, g_sdst[i]);
    }
    #pragma unroll
    for (int o = 16; o > 0; o >>= 1) {
        ms = fmaxf(ms, __shfl_xor_sync(0xFFFFFFFFu, ms, o));
        md = fmaxf(md, __shfl_xor_sync(0xFFFFFFFFu, md, o));
    }
    __shared__ float sms[8], smd[8];
    int wid = threadIdx.x >> 5;
    if ((threadIdx.x & 31) == 0) { sms[wid] = ms; smd[wid] = md; }
    __syncthreads();
    if (threadIdx.x == 0) {
        float bs = sms[0], bd = smd[0];
        for (int i = 1; i < (int)(blockDim.x >> 5); i++) {
            bs = fmaxf(bs, sms[i]); bd = fmaxf(bd, smd[i]);
        }
        atomicMax(&g_maxs_enc, float_enc(bs));
        atomicMax(&g_maxd_enc, float_enc(bd));
    }
}

__global__ void decode_kernel() {
    g_shiftC = float_dec(g_maxs_enc) + float_dec(g_maxd_enc);
}

// ---------------- kernel 5: count histogram by src ---------------------------
__global__ void hist_kernel(const void* __restrict__ edge, int E) {
    int is64 = g_is64;
    for (long long e = (long long)blockIdx.x * blockDim.x + threadIdx.x; e < E;
         e += (long long)gridDim.x * blockDim.x) {
        int u = get_idx(edge, e, is64);
        atomicAdd(&g_count[u], 1);
    }
}

// ---------------- scan kernels: exclusive prefix sum of g_count -> g_offset --
__global__ __launch_bounds__(1024) void scan1_kernel(int N) {
    __shared__ int s[1024];
    int tid = threadIdx.x;
    int i = blockIdx.x * 1024 + tid;
    int v = (i < N) ? g_count[i] : 0;
    s[tid] = v;
    __syncthreads();
    #pragma unroll
    for (int off = 1; off < 1024; off <<= 1) {
        int t = (tid >= off) ? s[tid - off] : 0;
        __syncthreads();
        s[tid] += t;
        __syncthreads();
    }
    if (i < N) g_offset[i] = s[tid] - v;
    if (tid == 1023) g_bsum[blockIdx.x] = s[1023];
}

__global__ __launch_bounds__(128) void scan2_kernel(int nb) {
    __shared__ int s[128];
    int tid = threadIdx.x;
    int v = (tid < nb) ? g_bsum[tid] : 0;
    s[tid] = v;
    __syncthreads();
    #pragma unroll
    for (int off = 1; off < 128; off <<= 1) {
        int t = (tid >= off) ? s[tid - off] : 0;
        __syncthreads();
        s[tid] += t;
        __syncthreads();
    }
    if (tid < nb) g_bsum[tid] = s[tid] - v;
}

__global__ void scan3_kernel(int N, int E) {
    int i = blockIdx.x * blockDim.x + threadIdx.x;
    if (i < N) {
        int off = g_offset[i] + g_bsum[i >> 10];
        g_offset[i] = off;
        g_cursor[i] = off;
    }
    if (i == 0) g_offset[N] = E;
}

// ---------------- kernel 6: place edges sorted by src ------------------------
__global__ void place_kernel(const void* __restrict__ edge, int E) {
    int is64 = g_is64;
    for (long long e = (long long)blockIdx.x * blockDim.x + threadIdx.x; e < E;
         e += (long long)gridDim.x * blockDim.x) {
        int u = get_idx(edge, e, is64);
        int v = get_idx(edge, (long long)E + e, is64);
        int pos = atomicAdd(&g_cursor[u], 1);
        g_dst32[pos] = v;
    }
}

// ---------------- kernel 7: per-node aggregate (fp16 gather) + finalize ------
__global__ __launch_bounds__(256) void agg_kernel(float* __restrict__ out, int N) {
    int u = (blockIdx.x * blockDim.x + threadIdx.x) >> 5;
    if (u >= N) return;
    int lane = threadIdx.x & 31;
    int beg = g_offset[u], end = g_offset[u + 1];
    float su = g_ssrc[u];
    float C = g_shiftC;
    float acc[8];
    #pragma unroll
    for (int j = 0; j < 8; j++) acc[j] = 0.f;
    float rs = 0.f;

    for (int base = beg; base < end; base += 32) {
        int cnt = min(32, end - base);
        int v = 0; float wg = 0.f;
        if (lane < cnt) {
            v = g_dst32[base + lane];
            float z = su + g_sdst[v];
            z = (z > 0.f) ? z : ALPHA * z;
            wg = __expf(z - C);
        }
        for (int i = 0; i < cnt; i++) {
            int vi = __shfl_sync(0xFFFFFFFFu, v, i);
            float wi = __shfl_sync(0xFFFFFFFFu, wg, i);
            uint4 raw = *((const uint4*)(g_h16 + (size_t)vi * F_OUT) + lane);
            const __half2* hp = (const __half2*)&raw;
            #pragma unroll
            for (int j = 0; j < 4; j++) {
                float2 f = __half22float2(hp[j]);
                acc[2 * j + 0] += wi * f.x;
                acc[2 * j + 1] += wi * f.y;
            }
            rs += wi;
        }
    }
    float inv = 1.f / (rs + EPS_DEN);
    float o[8];
    #pragma unroll
    for (int j = 0; j < 8; j++) {
        float v = acc[j] * inv;
        o[j] = (v > 0.f) ? v : expm1f(v);
    }
    float4* op = (float4*)(out + (size_t)u * F_OUT) + lane * 2;
    op[0] = make_float4(o[0], o[1], o[2], o[3]);
    op[1] = make_float4(o[4], o[5], o[6], o[7]);
}

// ---------------- launch ----------------
extern "C" void kernel_launch(void* const* d_in, const int* in_sizes, int n_in,
                              void* d_out, int out_size)
{
    const float* x    = (const float*)d_in[0];
    const void*  edge = d_in[1];
    const float* W    = (const float*)d_in[2];
    const float* a    = (const float*)d_in[3];
    const float* bias = (const float*)d_in[4];
    float* out = (float*)d_out;

    int N = in_sizes[0] / F_IN;
    int E = in_sizes[1] / 2;

    static int smem_set = 0;
    if (!smem_set) {
        cudaFuncSetAttribute(gemm_mma_kernel, cudaFuncAttributeMaxDynamicSharedMemorySize, SM_TOTAL);
        smem_set = 1;
    }

    int nb_scan = (N + 1023) / 1024;

    probe_kernel<<<1, 1>>>((const unsigned long long*)edge);
    wsplit_kernel<<<(F_IN * F_OUT + 255) / 256, 256>>>(W);
    init_kernel<<<(N + 255) / 256, 256>>>(N);
    gemm_mma_kernel<<<(N + 63) / 64, 256, SM_TOTAL>>>(x, bias, a, N);
    nodemax_kernel<<<148, 256>>>(N);
    decode_kernel<<<1, 1>>>();
    hist_kernel<<<1024, 256>>>(edge, E);
    scan1_kernel<<<nb_scan, 1024>>>(N);
    scan2_kernel<<<1, 128>>>(nb_scan);
    scan3_kernel<<<(N + 255) / 256, 256>>>(N, E);
    place_kernel<<<1024, 256>>>(edge, E);
    {
        long long threads = (long long)N * 32;
        agg_kernel<<<(int)((threads + 255) / 256), 256>>>(out, N);
    }
}